// round 5
// baseline (speedup 1.0000x reference)
#include <cuda_runtime.h>
#include <cuda_bf16.h>
#include <cstdint>

#define BINS 10
#define NBLOCKS 592            // 148 SMs * 4 CTAs
#define NTHREADS 256
#define NWARPS (NTHREADS / 32)

__device__ double g_bce[BINS];       // zero at load; last block resets each call
__device__ float  g_cnt[BINS];
__device__ unsigned int g_done = 0;

// label_weight is exactly 0.0f or 1.0f -> bce*w / w are the masked contributions
__device__ __forceinline__ void proc(float x, float t, float w,
                                     unsigned long long* bank) {
    float e   = __expf(-fabsf(x));
    float ope = 1.0f + e;
    float inv = __fdividef(1.0f, ope);            // MUFU.RCP
    float s   = (x >= 0.0f) ? inv : (1.0f - inv); // sigmoid(x)
    float g   = fabsf(s - t);
    int bin   = min((int)(g * (float)BINS), BINS - 1);

    float lg  = __logf(ope);                      // log(1+e)
    float bce = fmaxf(x, 0.0f) + lg - x * t;

    float bv = bce * w;   // w in {0,1}
    float cv = w;

    unsigned long long add;
    asm("mov.b64 %0, {%1, %2};" : "=l"(add) : "f"(bv), "f"(cv));

    unsigned long long* cell = bank + (bin << 5);   // bin stride = 32 lanes
    unsigned long long old = *cell;
    unsigned long long nw;
    asm("add.rn.f32x2 %0, %1, %2;" : "=l"(nw) : "l"(old), "l"(add));
    *cell = nw;
}

__global__ void __launch_bounds__(NTHREADS, 4)
ghm_fused_kernel(const float* __restrict__ pred,
                 const float* __restrict__ target,
                 const float* __restrict__ lw,
                 float* __restrict__ out,
                 int n) {
    // Two independent banks -> two interleavable RMW chains
    __shared__ unsigned long long histA[NWARPS][BINS][32];
    __shared__ unsigned long long histB[NWARPS][BINS][32];
    __shared__ float s_b[BINS];
    __shared__ float s_c[BINS];
    __shared__ bool s_last;

    const int warp = threadIdx.x >> 5;
    const int lane = threadIdx.x & 31;

#pragma unroll
    for (int b = 0; b < BINS; b++) {
        histA[warp][b][lane] = 0ull;
        histB[warp][b][lane] = 0ull;
    }
    if (threadIdx.x < BINS) { s_b[threadIdx.x] = 0.0f; s_c[threadIdx.x] = 0.0f; }
    __syncthreads();

    unsigned long long* bankA = &histA[warp][0][lane];
    unsigned long long* bankB = &histB[warp][0][lane];

    const int tid    = blockIdx.x * blockDim.x + threadIdx.x;
    const int stride = gridDim.x * blockDim.x;
    const int n4     = n >> 2;

    const float4* p4 = (const float4*)pred;
    const float4* t4 = (const float4*)target;
    const float4* w4 = (const float4*)lw;

    int i = tid;
    if (i + stride < n4) {
        // prologue: prefetch first double-batch
        float4 pa = __ldcs(&p4[i]);
        float4 ta = __ldcs(&t4[i]);
        float4 wa = __ldcs(&w4[i]);
        float4 pb = __ldcs(&p4[i + stride]);
        float4 tb = __ldcs(&t4[i + stride]);
        float4 wb = __ldcs(&w4[i + stride]);

        // pipelined main loop: issue next loads, then process current
        for (; i + 3 * stride < n4; ) {
            const int j = i + 2 * stride;
            float4 npa = __ldcs(&p4[j]);
            float4 nta = __ldcs(&t4[j]);
            float4 nwa = __ldcs(&w4[j]);
            float4 npb = __ldcs(&p4[j + stride]);
            float4 ntb = __ldcs(&t4[j + stride]);
            float4 nwb = __ldcs(&w4[j + stride]);

            proc(pa.x, ta.x, wa.x, bankA);
            proc(pa.y, ta.y, wa.y, bankB);
            proc(pa.z, ta.z, wa.z, bankA);
            proc(pa.w, ta.w, wa.w, bankB);
            proc(pb.x, tb.x, wb.x, bankA);
            proc(pb.y, tb.y, wb.y, bankB);
            proc(pb.z, tb.z, wb.z, bankA);
            proc(pb.w, tb.w, wb.w, bankB);

            pa = npa; ta = nta; wa = nwa;
            pb = npb; tb = ntb; wb = nwb;
            i = j;
        }
        // epilogue for the in-flight double-batch
        proc(pa.x, ta.x, wa.x, bankA);
        proc(pa.y, ta.y, wa.y, bankB);
        proc(pa.z, ta.z, wa.z, bankA);
        proc(pa.w, ta.w, wa.w, bankB);
        proc(pb.x, tb.x, wb.x, bankA);
        proc(pb.y, tb.y, wb.y, bankB);
        proc(pb.z, tb.z, wb.z, bankA);
        proc(pb.w, tb.w, wb.w, bankB);
        i += 2 * stride;
    }
    // remaining single batches
    for (; i < n4; i += stride) {
        float4 p = __ldcs(&p4[i]);
        float4 t = __ldcs(&t4[i]);
        float4 w = __ldcs(&w4[i]);
        proc(p.x, t.x, w.x, bankA);
        proc(p.y, t.y, w.y, bankB);
        proc(p.z, t.z, w.z, bankA);
        proc(p.w, t.w, w.w, bankB);
    }
    // scalar tail
    for (int j = (n4 << 2) + tid; j < n; j += stride) {
        proc(pred[j], target[j], lw[j], bankA);
    }
    __syncwarp();

    // per-warp reduce: each lane owns histA/B[warp][b][lane]
#pragma unroll
    for (int b = 0; b < BINS; b++) {
        unsigned long long va = histA[warp][b][lane];
        unsigned long long vbk = histB[warp][b][lane];
        float a0, a1, b0, b1;
        asm("mov.b64 {%0, %1}, %2;" : "=f"(a0), "=f"(a1) : "l"(va));
        asm("mov.b64 {%0, %1}, %2;" : "=f"(b0), "=f"(b1) : "l"(vbk));
        float vb = a0 + b0;
        float vc = a1 + b1;
#pragma unroll
        for (int o = 16; o > 0; o >>= 1) {
            vb += __shfl_down_sync(0xffffffffu, vb, o);
            vc += __shfl_down_sync(0xffffffffu, vc, o);
        }
        if (lane == 0) {
            atomicAdd(&s_b[b], vb);
            atomicAdd(&s_c[b], vc);
        }
    }
    __syncthreads();

    if (threadIdx.x < BINS) {
        atomicAdd(&g_bce[threadIdx.x], (double)s_b[threadIdx.x]);
        atomicAdd(&g_cnt[threadIdx.x], s_c[threadIdx.x]);
    }

    // last-block finalize
    __threadfence();
    if (threadIdx.x == 0) {
        unsigned int v = atomicAdd(&g_done, 1u);
        s_last = (v == (unsigned int)(gridDim.x - 1));
    }
    __syncthreads();

    if (s_last && threadIdx.x == 0) {
        double tot = 0.0;
        int nb = 0;
        for (int b = 0; b < BINS; b++) {
            tot += (double)g_cnt[b];
            if (g_cnt[b] > 0.0f) nb++;
        }
        double totm = tot > 1.0 ? tot : 1.0;
        double nm = (nb > 1) ? (double)nb : 1.0;
        double loss = 0.0;
        for (int b = 0; b < BINS; b++) {
            if (g_cnt[b] > 0.0f) {
                double wpb = (totm / (double)g_cnt[b]) / nm;
                loss += wpb * g_bce[b];
            }
        }
        loss /= totm;
        out[0] = (float)loss;  // LOSS_WEIGHT = 1.0

        for (int b = 0; b < BINS; b++) { g_bce[b] = 0.0; g_cnt[b] = 0.0f; }
        g_done = 0;
    }
}

extern "C" void kernel_launch(void* const* d_in, const int* in_sizes, int n_in,
                              void* d_out, int out_size) {
    const float* pred   = (const float*)d_in[0];
    const float* target = (const float*)d_in[1];
    const float* lw     = (const float*)d_in[2];
    float* out = (float*)d_out;
    int n = in_sizes[0];

    ghm_fused_kernel<<<NBLOCKS, NTHREADS>>>(pred, target, lw, out, n);
}

// round 6
// speedup vs baseline: 1.2172x; 1.2172x over previous
#include <cuda_runtime.h>
#include <cuda_bf16.h>
#include <cstdint>

#define BINS 10
#define NBLOCKS 592            // 148 SMs * 4 CTAs
#define NTHREADS 256
#define NWARPS (NTHREADS / 32)

__device__ double g_bce[BINS];       // zero at load; last block resets each call
__device__ float  g_cnt[BINS];
__device__ unsigned int g_done = 0;

// label_weight is exactly 0.0f or 1.0f -> bce*w / w are the masked contributions
__device__ __forceinline__ void proc(float x, float t, float w,
                                     unsigned long long* myhist) {
    float e   = __expf(-fabsf(x));
    float ope = 1.0f + e;
    float inv = __fdividef(1.0f, ope);            // MUFU.RCP
    float s   = (x >= 0.0f) ? inv : (1.0f - inv); // sigmoid(x)
    float g   = fabsf(s - t);
    int bin   = min((int)(g * (float)BINS), BINS - 1);

    float lg  = __logf(ope);                      // log(1+e)
    float bce = fmaxf(x, 0.0f) + lg - x * t;

    float bv = bce * w;   // w in {0,1}
    float cv = w;

    unsigned long long add;
    asm("mov.b64 %0, {%1, %2};" : "=l"(add) : "f"(bv), "f"(cv));

    unsigned long long* cell = myhist + (bin << 5);   // bin stride = 32 lanes
    unsigned long long old = *cell;
    unsigned long long nw;
    asm("add.rn.f32x2 %0, %1, %2;" : "=l"(nw) : "l"(old), "l"(add));
    *cell = nw;
}

__global__ void __launch_bounds__(NTHREADS, 4)
ghm_fused_kernel(const float* __restrict__ pred,
                 const float* __restrict__ target,
                 const float* __restrict__ lw,
                 float* __restrict__ out,
                 int n) {
    __shared__ unsigned long long hist[NWARPS][BINS][32];
    __shared__ float s_b[BINS];
    __shared__ float s_c[BINS];
    __shared__ bool s_last;

    const int warp = threadIdx.x >> 5;
    const int lane = threadIdx.x & 31;

#pragma unroll
    for (int b = 0; b < BINS; b++) hist[warp][b][lane] = 0ull;
    if (threadIdx.x < BINS) { s_b[threadIdx.x] = 0.0f; s_c[threadIdx.x] = 0.0f; }
    __syncthreads();

    unsigned long long* myhist = &hist[warp][0][lane];

    const int tid    = blockIdx.x * blockDim.x + threadIdx.x;
    const int stride = gridDim.x * blockDim.x;
    const int n4     = n >> 2;

    const float4* p4 = (const float4*)pred;
    const float4* t4 = (const float4*)target;
    const float4* w4 = (const float4*)lw;

    int i = tid;
    // 3x-unrolled main loop: 9 LDG.128 front-batched for MLP
    for (; i + 2 * stride < n4; i += 3 * stride) {
        const int i1 = i + stride;
        const int i2 = i + 2 * stride;
        float4 pa = __ldcs(&p4[i]);
        float4 ta = __ldcs(&t4[i]);
        float4 wa = __ldcs(&w4[i]);
        float4 pb = __ldcs(&p4[i1]);
        float4 tb = __ldcs(&t4[i1]);
        float4 wb = __ldcs(&w4[i1]);
        float4 pc = __ldcs(&p4[i2]);
        float4 tc = __ldcs(&t4[i2]);
        float4 wc = __ldcs(&w4[i2]);
        proc(pa.x, ta.x, wa.x, myhist);
        proc(pa.y, ta.y, wa.y, myhist);
        proc(pa.z, ta.z, wa.z, myhist);
        proc(pa.w, ta.w, wa.w, myhist);
        proc(pb.x, tb.x, wb.x, myhist);
        proc(pb.y, tb.y, wb.y, myhist);
        proc(pb.z, tb.z, wb.z, myhist);
        proc(pb.w, tb.w, wb.w, myhist);
        proc(pc.x, tc.x, wc.x, myhist);
        proc(pc.y, tc.y, wc.y, myhist);
        proc(pc.z, tc.z, wc.z, myhist);
        proc(pc.w, tc.w, wc.w, myhist);
    }
    for (; i < n4; i += stride) {
        float4 p = __ldcs(&p4[i]);
        float4 t = __ldcs(&t4[i]);
        float4 w = __ldcs(&w4[i]);
        proc(p.x, t.x, w.x, myhist);
        proc(p.y, t.y, w.y, myhist);
        proc(p.z, t.z, w.z, myhist);
        proc(p.w, t.w, w.w, myhist);
    }
    for (int j = (n4 << 2) + tid; j < n; j += stride) {
        proc(pred[j], target[j], lw[j], myhist);
    }
    __syncwarp();

    // per-warp reduce: each lane owns hist[warp][b][lane]
#pragma unroll
    for (int b = 0; b < BINS; b++) {
        unsigned long long v = hist[warp][b][lane];
        float vb, vc;
        asm("mov.b64 {%0, %1}, %2;" : "=f"(vb), "=f"(vc) : "l"(v));
#pragma unroll
        for (int o = 16; o > 0; o >>= 1) {
            vb += __shfl_down_sync(0xffffffffu, vb, o);
            vc += __shfl_down_sync(0xffffffffu, vc, o);
        }
        if (lane == 0) {
            atomicAdd(&s_b[b], vb);
            atomicAdd(&s_c[b], vc);
        }
    }
    __syncthreads();

    if (threadIdx.x < BINS) {
        atomicAdd(&g_bce[threadIdx.x], (double)s_b[threadIdx.x]);
        atomicAdd(&g_cnt[threadIdx.x], s_c[threadIdx.x]);
    }

    // last-block finalize
    __threadfence();
    if (threadIdx.x == 0) {
        unsigned int v = atomicAdd(&g_done, 1u);
        s_last = (v == (unsigned int)(gridDim.x - 1));
    }
    __syncthreads();

    if (s_last && threadIdx.x == 0) {
        double tot = 0.0;
        int nb = 0;
        for (int b = 0; b < BINS; b++) {
            tot += (double)g_cnt[b];
            if (g_cnt[b] > 0.0f) nb++;
        }
        double totm = tot > 1.0 ? tot : 1.0;
        double nm = (nb > 1) ? (double)nb : 1.0;
        double loss = 0.0;
        for (int b = 0; b < BINS; b++) {
            if (g_cnt[b] > 0.0f) {
                double wpb = (totm / (double)g_cnt[b]) / nm;
                loss += wpb * g_bce[b];
            }
        }
        loss /= totm;
        out[0] = (float)loss;  // LOSS_WEIGHT = 1.0

        for (int b = 0; b < BINS; b++) { g_bce[b] = 0.0; g_cnt[b] = 0.0f; }
        g_done = 0;
    }
}

extern "C" void kernel_launch(void* const* d_in, const int* in_sizes, int n_in,
                              void* d_out, int out_size) {
    const float* pred   = (const float*)d_in[0];
    const float* target = (const float*)d_in[1];
    const float* lw     = (const float*)d_in[2];
    float* out = (float*)d_out;
    int n = in_sizes[0];

    ghm_fused_kernel<<<NBLOCKS, NTHREADS>>>(pred, target, lw, out, n);
}